// round 13
// baseline (speedup 1.0000x reference)
#include <cuda_runtime.h>
#include <cuda_fp16.h>
#include <math_constants.h>
#include <cstdint>

#define B_ 4
#define N_ 20000
#define F_ 256
#define H_ 8
#define D_ 32
#define E_ 320000
#define M_ (B_ * N_)   // 80000 rows in flattened GEMM

// ---------------------------------------------------------------------------
// Scratch
// ---------------------------------------------------------------------------
__device__ __half   g_hp16[(size_t)M_ * F_];        // [B,N,H,D] fp16 (~41MB)
__device__ float    g_asrc[(size_t)M_ * H_];        // [B,N,H]
__device__ float    g_atrg[(size_t)M_ * H_];        // [B,N,H]
__device__ int      g_counts[M_];                   // per (b,n) in-degree
__device__ int      g_offsets[M_];                  // scan; fill bumps to END
__device__ int      g_sorted_src[(size_t)B_ * E_]; // CSR payload: src per slot
__device__ int      g_segsum[64];                   // scan phase partials

#define SCAN_SEGS 10
#define SCAN_SEG_LEN 2000
#define SCAN_PER_THR 8

// GEMM chunk split: chunk0 covers row-blocks [0,313) = rows [0,40064) ⊇ batches 0,1
#define GEMM_SPLIT 313

// ---------------------------------------------------------------------------
// helpers
// ---------------------------------------------------------------------------
__device__ __forceinline__ void mma_fp16(float c[4], uint32_t a0, uint32_t a1,
                                         uint32_t a2, uint32_t a3,
                                         uint32_t b0, uint32_t b1) {
    asm volatile(
        "mma.sync.aligned.m16n8k16.row.col.f32.f16.f16.f32 "
        "{%0,%1,%2,%3},{%4,%5,%6,%7},{%8,%9},{%0,%1,%2,%3};"
        : "+f"(c[0]), "+f"(c[1]), "+f"(c[2]), "+f"(c[3])
        : "r"(a0), "r"(a1), "r"(a2), "r"(a3), "r"(b0), "r"(b1));
}

__device__ __forceinline__ float leaky_exp(float x) {
    x = x > 0.f ? x : 0.2f * x;
    return __expf(x);
}

// ---------------------------------------------------------------------------
// 0) init: zero counts only
// ---------------------------------------------------------------------------
__global__ void init_kernel() {
    int i = blockIdx.x * blockDim.x + threadIdx.x;
    if (i < M_) g_counts[i] = 0;
}

// ---------------------------------------------------------------------------
// 1) fp16 GEMM (fp32 accum), chunked over M via bx0 block offset.
// ---------------------------------------------------------------------------
#define BK_ 16
#define BKP_ 24
__global__ __launch_bounds__(256) void gemm_fp16_kernel(const float* __restrict__ A,
                                                        const float* __restrict__ W,
                                                        const float* __restrict__ attn_src,
                                                        const float* __restrict__ attn_trg,
                                                        int bx0) {
    __shared__ __half As[128][BKP_];
    __shared__ __half Bs[128][BKP_];

    const int tid   = threadIdx.x;
    const int lane  = tid & 31;
    const int wid   = tid >> 5;
    const int warpM = wid >> 2;
    const int warpN = wid & 3;
    const int bm    = (blockIdx.x + bx0) * 128;
    const int bn    = blockIdx.y * 128;

    const int lr = tid >> 2;
    const int lc = (tid & 3) * 4;

    float c[4][4][4];
#pragma unroll
    for (int i = 0; i < 4; i++)
#pragma unroll
        for (int j = 0; j < 4; j++)
#pragma unroll
            for (int q = 0; q < 4; q++) c[i][j][q] = 0.f;

    float4 av0 = *(const float4*)(A + (size_t)(bm + lr) * 256 + lc);
    float4 av1 = *(const float4*)(A + (size_t)(bm + lr + 64) * 256 + lc);
    float4 bv0 = *(const float4*)(W + (size_t)(bn + lr) * 256 + lc);
    float4 bv1 = *(const float4*)(W + (size_t)(bn + lr + 64) * 256 + lc);

    const int r = lane >> 2;
    const int q = lane & 3;

    for (int k0 = 0; k0 < 256; k0 += BK_) {
        *(__half2*)&As[lr][lc]          = __floats2half2_rn(av0.x, av0.y);
        *(__half2*)&As[lr][lc + 2]      = __floats2half2_rn(av0.z, av0.w);
        *(__half2*)&As[lr + 64][lc]     = __floats2half2_rn(av1.x, av1.y);
        *(__half2*)&As[lr + 64][lc + 2] = __floats2half2_rn(av1.z, av1.w);
        *(__half2*)&Bs[lr][lc]          = __floats2half2_rn(bv0.x, bv0.y);
        *(__half2*)&Bs[lr][lc + 2]      = __floats2half2_rn(bv0.z, bv0.w);
        *(__half2*)&Bs[lr + 64][lc]     = __floats2half2_rn(bv1.x, bv1.y);
        *(__half2*)&Bs[lr + 64][lc + 2] = __floats2half2_rn(bv1.z, bv1.w);
        __syncthreads();

        if (k0 + BK_ < 256) {
            av0 = *(const float4*)(A + (size_t)(bm + lr) * 256 + k0 + BK_ + lc);
            av1 = *(const float4*)(A + (size_t)(bm + lr + 64) * 256 + k0 + BK_ + lc);
            bv0 = *(const float4*)(W + (size_t)(bn + lr) * 256 + k0 + BK_ + lc);
            bv1 = *(const float4*)(W + (size_t)(bn + lr + 64) * 256 + k0 + BK_ + lc);
        }

        uint32_t a[4][4], bf[4][2];
#pragma unroll
        for (int i = 0; i < 4; i++) {
            int row = warpM * 64 + i * 16;
            a[i][0] = *(const uint32_t*)&As[row + r][2 * q];
            a[i][1] = *(const uint32_t*)&As[row + r + 8][2 * q];
            a[i][2] = *(const uint32_t*)&As[row + r][2 * q + 8];
            a[i][3] = *(const uint32_t*)&As[row + r + 8][2 * q + 8];
        }
#pragma unroll
        for (int j = 0; j < 4; j++) {
            int col = warpN * 32 + j * 8 + r;
            bf[j][0] = *(const uint32_t*)&Bs[col][2 * q];
            bf[j][1] = *(const uint32_t*)&Bs[col][2 * q + 8];
        }
#pragma unroll
        for (int i = 0; i < 4; i++)
#pragma unroll
            for (int j = 0; j < 4; j++)
                mma_fp16(c[i][j], a[i][0], a[i][1], a[i][2], a[i][3],
                         bf[j][0], bf[j][1]);
        __syncthreads();
    }

    const int head = (bn >> 5) + warpN;

    float ws[8], wt[8];
#pragma unroll
    for (int j = 0; j < 4; j++) {
        int col = head * 32 + j * 8 + 2 * q;
        ws[2 * j + 0] = __ldg(&attn_src[col]);
        ws[2 * j + 1] = __ldg(&attn_src[col + 1]);
        wt[2 * j + 0] = __ldg(&attn_trg[col]);
        wt[2 * j + 1] = __ldg(&attn_trg[col + 1]);
    }

#pragma unroll
    for (int i = 0; i < 4; i++) {
        int m0 = bm + warpM * 64 + i * 16 + r;
        float s0 = 0.f, s1 = 0.f, t0 = 0.f, t1 = 0.f;
#pragma unroll
        for (int j = 0; j < 4; j++) {
            __half* base = g_hp16 + (size_t)m0 * 256 + bn + warpN * 32 + j * 8 + 2 * q;
            *(__half2*)base = __floats2half2_rn(c[i][j][0], c[i][j][1]);
            *(__half2*)(base + 8 * 256) = __floats2half2_rn(c[i][j][2], c[i][j][3]);
            s0 += c[i][j][0] * ws[2 * j] + c[i][j][1] * ws[2 * j + 1];
            s1 += c[i][j][2] * ws[2 * j] + c[i][j][3] * ws[2 * j + 1];
            t0 += c[i][j][0] * wt[2 * j] + c[i][j][1] * wt[2 * j + 1];
            t1 += c[i][j][2] * wt[2 * j] + c[i][j][3] * wt[2 * j + 1];
        }
#pragma unroll
        for (int o = 1; o < 4; o <<= 1) {
            s0 += __shfl_xor_sync(0xffffffffu, s0, o);
            s1 += __shfl_xor_sync(0xffffffffu, s1, o);
            t0 += __shfl_xor_sync(0xffffffffu, t0, o);
            t1 += __shfl_xor_sync(0xffffffffu, t1, o);
        }
        if (q == 0) {
            g_asrc[(size_t)m0 * H_ + head]       = s0;
            g_asrc[(size_t)(m0 + 8) * H_ + head] = s1;
            g_atrg[(size_t)m0 * H_ + head]       = t0;
            g_atrg[(size_t)(m0 + 8) * H_ + head] = t1;
        }
    }
}

// ---------------------------------------------------------------------------
// 2) histogram of targets (batch offset b0)
// ---------------------------------------------------------------------------
__global__ __launch_bounds__(256) void hist_kernel(const int* __restrict__ ei, int b0) {
    int b = blockIdx.y + b0;
    int e = blockIdx.x * 256 + threadIdx.x;
    if (e < E_) {
        int trg = ei[(size_t)b * 2 * E_ + E_ + e];
        atomicAdd(&g_counts[b * N_ + trg], 1);
    }
}

// ---------------------------------------------------------------------------
// 3) scan, 2-phase (segment offset seg0)
// ---------------------------------------------------------------------------
__global__ __launch_bounds__(256) void scan1_kernel(int seg0) {
    const int seg  = blockIdx.x + seg0;
    const int base = seg * SCAN_SEG_LEN;
    int local = 0;
    for (int i = threadIdx.x; i < SCAN_SEG_LEN; i += 256)
        local += g_counts[base + i];
#pragma unroll
    for (int o = 16; o > 0; o >>= 1) local += __shfl_xor_sync(0xffffffffu, local, o);
    __shared__ int warpsum[8];
    if ((threadIdx.x & 31) == 0) warpsum[threadIdx.x >> 5] = local;
    __syncthreads();
    if (threadIdx.x == 0) {
        int s = 0;
#pragma unroll
        for (int w = 0; w < 8; w++) s += warpsum[w];
        g_segsum[seg] = s;
    }
}

__global__ __launch_bounds__(256) void scan3_kernel(int seg0) {
    const int seg  = blockIdx.x + seg0;
    const int base = seg * SCAN_SEG_LEN;
    const int tid  = threadIdx.x;
    __shared__ int sums[256];
    __shared__ int segbase;

    if (tid == 0) {
        int b = seg / SCAN_SEGS;
        int s = 0;
        for (int k = b * SCAN_SEGS; k < seg; k++) s += g_segsum[k];
        segbase = s;
    }

    int vals[SCAN_PER_THR];
    int tb = tid * SCAN_PER_THR;
    int local = 0;
#pragma unroll
    for (int i = 0; i < SCAN_PER_THR; i++) {
        int idx = tb + i;
        vals[i] = (idx < SCAN_SEG_LEN) ? g_counts[base + idx] : 0;
        local += vals[i];
    }
    int v = local;
    int lane = tid & 31, w = tid >> 5;
#pragma unroll
    for (int o = 1; o < 32; o <<= 1) {
        int u = __shfl_up_sync(0xffffffffu, v, o);
        if (lane >= o) v += u;
    }
    __shared__ int wsum[8];
    if (lane == 31) wsum[w] = v;
    __syncthreads();
    if (tid < 8) {
        int u = wsum[tid];
#pragma unroll
        for (int o = 1; o < 8; o <<= 1) {
            int p = __shfl_up_sync(0xffu, u, o);
            if (tid >= o) u += p;
        }
        sums[tid] = u;
    }
    __syncthreads();
    int prefix = v - local + (w > 0 ? sums[w - 1] : 0) + segbase;
#pragma unroll
    for (int i = 0; i < SCAN_PER_THR; i++) {
        int idx = tb + i;
        if (idx < SCAN_SEG_LEN) {
            g_offsets[base + idx] = prefix;
            prefix += vals[i];
        }
    }
}

// ---------------------------------------------------------------------------
// 4) fill CSR buckets (batch offset b0); bumps g_offsets -> END
// ---------------------------------------------------------------------------
__global__ __launch_bounds__(256) void fill_kernel(const int* __restrict__ ei, int b0) {
    int b = blockIdx.y + b0;
    int e = blockIdx.x * 256 + threadIdx.x;
    if (e >= E_) return;
    int src = ei[(size_t)b * 2 * E_ + e];
    int trg = ei[(size_t)b * 2 * E_ + E_ + e];
    int pos = atomicAdd(&g_offsets[b * N_ + trg], 1);
    g_sorted_src[(size_t)b * E_ + pos] = src;
}

// ---------------------------------------------------------------------------
// 5) gather-aggregate: one warp per node, all 8 heads (batch offset b0).
// ---------------------------------------------------------------------------
__global__ __launch_bounds__(256) void aggregate_kernel(float* __restrict__ out, int b0) {
    const int tid  = threadIdx.x;
    const int wid  = tid >> 5;
    const int lane = tid & 31;
    const int n    = blockIdx.x * 8 + wid;
    const int b    = blockIdx.y + b0;

    __shared__ int   s_src[8][32];
    __shared__ float s_w[8][32][8];

    const int deg = g_counts[b * N_ + n];
    const int off = g_offsets[b * N_ + n] - deg;   // offsets = end after fill

    const float4 at0 = *(const float4*)(g_atrg + (size_t)(b * N_ + n) * H_);
    const float4 at1 = *(const float4*)(g_atrg + (size_t)(b * N_ + n) * H_ + 4);

    const int*    srcs = g_sorted_src + (size_t)b * E_ + off;
    const float*  asb  = g_asrc + (size_t)b * N_ * H_;
    const __half* hpb  = g_hp16 + (size_t)b * N_ * 256;

    const int hgrp = lane >> 3;
    const int dofs = 4 * lane;

    float4 acc0 = make_float4(0.f, 0.f, 0.f, 0.f);
    float4 acc1 = make_float4(0.f, 0.f, 0.f, 0.f);
    float  den0 = 0.f, den1 = 0.f;

    for (int c0 = 0; c0 < deg; c0 += 32) {
        const int cnt = min(32, deg - c0);
        if (lane < cnt) {
            int src = __ldg(srcs + c0 + lane);
            s_src[wid][lane] = src;
            const float4 a0 = *(const float4*)(asb + (size_t)src * H_);
            const float4 a1 = *(const float4*)(asb + (size_t)src * H_ + 4);
            s_w[wid][lane][0] = leaky_exp(a0.x + at0.x);
            s_w[wid][lane][2] = leaky_exp(a0.y + at0.y);
            s_w[wid][lane][4] = leaky_exp(a0.z + at0.z);
            s_w[wid][lane][6] = leaky_exp(a0.w + at0.w);
            s_w[wid][lane][1] = leaky_exp(a1.x + at1.x);
            s_w[wid][lane][3] = leaky_exp(a1.y + at1.y);
            s_w[wid][lane][5] = leaky_exp(a1.z + at1.z);
            s_w[wid][lane][7] = leaky_exp(a1.w + at1.w);
        }
        __syncwarp();

        int j = 0;
        for (; j + 4 <= cnt; j += 4) {
            int   sA = s_src[wid][j],     sB = s_src[wid][j + 1];
            int   sC = s_src[wid][j + 2], sD = s_src[wid][j + 3];
            float2 wA = *(const float2*)&s_w[wid][j][2 * hgrp];
            float2 wB = *(const float2*)&s_w[wid][j + 1][2 * hgrp];
            float2 wC = *(const float2*)&s_w[wid][j + 2][2 * hgrp];
            float2 wD = *(const float2*)&s_w[wid][j + 3][2 * hgrp];
            const __half* rA = hpb + (size_t)sA * 256 + dofs;
            const __half* rB = hpb + (size_t)sB * 256 + dofs;
            const __half* rC = hpb + (size_t)sC * 256 + dofs;
            const __half* rD = hpb + (size_t)sD * 256 + dofs;
            uint2 pA0 = __ldg((const uint2*)rA);
            uint2 pA1 = __ldg((const uint2*)(rA + 128));
            uint2 pB0 = __ldg((const uint2*)rB);
            uint2 pB1 = __ldg((const uint2*)(rB + 128));
            uint2 pC0 = __ldg((const uint2*)rC);
            uint2 pC1 = __ldg((const uint2*)(rC + 128));
            uint2 pD0 = __ldg((const uint2*)rD);
            uint2 pD1 = __ldg((const uint2*)(rD + 128));
            den0 += (wA.x + wB.x) + (wC.x + wD.x);
            den1 += (wA.y + wB.y) + (wC.y + wD.y);
            float2 v0, v1, v2, v3;
            v0 = __half22float2(*(__half2*)&pA0.x); v1 = __half22float2(*(__half2*)&pA0.y);
            v2 = __half22float2(*(__half2*)&pA1.x); v3 = __half22float2(*(__half2*)&pA1.y);
            acc0.x = fmaf(wA.x, v0.x, acc0.x); acc0.y = fmaf(wA.x, v0.y, acc0.y);
            acc0.z = fmaf(wA.x, v1.x, acc0.z); acc0.w = fmaf(wA.x, v1.y, acc0.w);
            acc1.x = fmaf(wA.y, v2.x, acc1.x); acc1.y = fmaf(wA.y, v2.y, acc1.y);
            acc1.z = fmaf(wA.y, v3.x, acc1.z); acc1.w = fmaf(wA.y, v3.y, acc1.w);
            v0 = __half22float2(*(__half2*)&pB0.x); v1 = __half22float2(*(__half2*)&pB0.y);
            v2 = __half22float2(*(__half2*)&pB1.x); v3 = __half22float2(*(__half2*)&pB1.y);
            acc0.x = fmaf(wB.x, v0.x, acc0.x); acc0.y = fmaf(wB.x, v0.y, acc0.y);
            acc0.z = fmaf(wB.x, v1.x, acc0.z); acc0.w = fmaf(wB.x, v1.y, acc0.w);
            acc1.x = fmaf(wB.y, v2.x, acc1.x); acc1.y = fmaf(wB.y, v2.y, acc1.y);
            acc1.z = fmaf(wB.y, v3.x, acc1.z); acc1.w = fmaf(wB.y, v3.y, acc1.w);
            v0 = __half22float2(*(__half2*)&pC0.x); v1 = __half22float2(*(__half2*)&pC0.y);
            v2 = __half22float2(*(__half2*)&pC1.x); v3 = __half22float2(*(__half2*)&pC1.y);
            acc0.x = fmaf(wC.x, v0.x, acc0.x); acc0.y = fmaf(wC.x, v0.y, acc0.y);
            acc0.z = fmaf(wC.x, v1.x, acc0.z); acc0.w = fmaf(wC.x, v1.y, acc0.w);
            acc1.x = fmaf(wC.y, v2.x, acc1.x); acc1.y = fmaf(wC.y, v2.y, acc1.y);
            acc1.z = fmaf(wC.y, v3.x, acc1.z); acc1.w = fmaf(wC.y, v3.y, acc1.w);
            v0 = __half22float2(*(__half2*)&pD0.x); v1 = __half22float2(*(__half2*)&pD0.y);
            v2 = __half22float2(*(__half2*)&pD1.x); v3 = __half22float2(*(__half2*)&pD1.y);
            acc0.x = fmaf(wD.x, v0.x, acc0.x); acc0.y = fmaf(wD.x, v0.y, acc0.y);
            acc0.z = fmaf(wD.x, v1.x, acc0.z); acc0.w = fmaf(wD.x, v1.y, acc0.w);
            acc1.x = fmaf(wD.y, v2.x, acc1.x); acc1.y = fmaf(wD.y, v2.y, acc1.y);
            acc1.z = fmaf(wD.y, v3.x, acc1.z); acc1.w = fmaf(wD.y, v3.y, acc1.w);
        }
        for (; j < cnt; j++) {
            const int s = s_src[wid][j];
            const float2 w = *(const float2*)&s_w[wid][j][2 * hgrp];
            const __half* rr = hpb + (size_t)s * 256 + dofs;
            uint2 p0 = __ldg((const uint2*)rr);
            uint2 p1 = __ldg((const uint2*)(rr + 128));
            den0 += w.x; den1 += w.y;
            float2 a0 = __half22float2(*(__half2*)&p0.x);
            float2 a1 = __half22float2(*(__half2*)&p0.y);
            float2 a2 = __half22float2(*(__half2*)&p1.x);
            float2 a3 = __half22float2(*(__half2*)&p1.y);
            acc0.x = fmaf(w.x, a0.x, acc0.x); acc0.y = fmaf(w.x, a0.y, acc0.y);
            acc0.z = fmaf(w.x, a1.x, acc0.z); acc0.w = fmaf(w.x, a1.y, acc0.w);
            acc1.x = fmaf(w.y, a2.x, acc1.x); acc1.y = fmaf(w.y, a2.y, acc1.y);
            acc1.z = fmaf(w.y, a3.x, acc1.z); acc1.w = fmaf(w.y, a3.y, acc1.w);
        }
        __syncwarp();
    }

    const float i0 = 1.f / (den0 + 1e-16f);
    const float i1 = 1.f / (den1 + 1e-16f);
    const int d0 = 4 * (lane & 7);
    float4* o0 = (float4*)(out + (((size_t)b * H_ + hgrp) * N_ + n) * D_ + d0);
    float4* o1 = (float4*)(out + (((size_t)b * H_ + hgrp + 4) * N_ + n) * D_ + d0);
    *o0 = make_float4(acc0.x * i0, acc0.y * i0, acc0.z * i0, acc0.w * i0);
    *o1 = make_float4(acc1.x * i1, acc1.y * i1, acc1.z * i1, acc1.w * i1);
}

// ---------------------------------------------------------------------------
// kernel_launch — batch-pipelined 3-stream schedule:
//   main:  gemm chunk0 (rows<40064) -> gemm chunk1
//   side:  init -> prep{b0,b1} -> prep{b2,b3}
//   agg :  wait(g0,prep01) agg{b0,b1} ; wait(g1,prep23) agg{b2,b3}
// ---------------------------------------------------------------------------
extern "C" void kernel_launch(void* const* d_in, const int* in_sizes, int n_in,
                              void* d_out, int out_size) {
    const float* h        = (const float*)d_in[0];
    const int*   ei       = (const int*)d_in[1];
    const float* W        = (const float*)d_in[2];
    const float* attn_src = (const float*)d_in[3];
    const float* attn_trg = (const float*)d_in[4];
    float*       out      = (float*)d_out;

    static cudaStream_t s_side = nullptr, s_agg = nullptr;
    static cudaEvent_t  ev_fork = nullptr, ev_g0 = nullptr, ev_g1 = nullptr,
                        ev_p01 = nullptr, ev_p23 = nullptr, ev_done = nullptr;
    if (s_side == nullptr) {
        cudaStreamCreateWithFlags(&s_side, cudaStreamNonBlocking);
        cudaStreamCreateWithFlags(&s_agg, cudaStreamNonBlocking);
        cudaEventCreateWithFlags(&ev_fork, cudaEventDisableTiming);
        cudaEventCreateWithFlags(&ev_g0, cudaEventDisableTiming);
        cudaEventCreateWithFlags(&ev_g1, cudaEventDisableTiming);
        cudaEventCreateWithFlags(&ev_p01, cudaEventDisableTiming);
        cudaEventCreateWithFlags(&ev_p23, cudaEventDisableTiming);
        cudaEventCreateWithFlags(&ev_done, cudaEventDisableTiming);
    }

    // fork
    cudaEventRecord(ev_fork, 0);
    cudaStreamWaitEvent(s_side, ev_fork, 0);

    // ---- side stream: edge prep, batches {0,1} then {2,3} ----
    dim3 egrid((E_ + 255) / 256, 2);
    init_kernel<<<(M_ + 255) / 256, 256, 0, s_side>>>();
    hist_kernel<<<egrid, 256, 0, s_side>>>(ei, 0);
    scan1_kernel<<<2 * SCAN_SEGS, 256, 0, s_side>>>(0);
    scan3_kernel<<<2 * SCAN_SEGS, 256, 0, s_side>>>(0);
    fill_kernel<<<egrid, 256, 0, s_side>>>(ei, 0);
    cudaEventRecord(ev_p01, s_side);
    hist_kernel<<<egrid, 256, 0, s_side>>>(ei, 2);
    scan1_kernel<<<2 * SCAN_SEGS, 256, 0, s_side>>>(2 * SCAN_SEGS);
    scan3_kernel<<<2 * SCAN_SEGS, 256, 0, s_side>>>(2 * SCAN_SEGS);
    fill_kernel<<<egrid, 256, 0, s_side>>>(ei, 2);
    cudaEventRecord(ev_p23, s_side);

    // ---- main stream: GEMM in two chunks ----
    dim3 ggrid0(GEMM_SPLIT, 2);                 // rows [0, 40064) ⊇ batches 0,1
    dim3 ggrid1(M_ / 128 - GEMM_SPLIT, 2);      // remaining rows
    gemm_fp16_kernel<<<ggrid0, 256>>>(h, W, attn_src, attn_trg, 0);
    cudaEventRecord(ev_g0, 0);
    gemm_fp16_kernel<<<ggrid1, 256>>>(h, W, attn_src, attn_trg, GEMM_SPLIT);
    cudaEventRecord(ev_g1, 0);

    // ---- agg stream: pipelined aggregates ----
    dim3 agrid(N_ / 8, 2);
    cudaStreamWaitEvent(s_agg, ev_g0, 0);
    cudaStreamWaitEvent(s_agg, ev_p01, 0);
    aggregate_kernel<<<agrid, 256, 0, s_agg>>>(out, 0);
    cudaStreamWaitEvent(s_agg, ev_g1, 0);
    cudaStreamWaitEvent(s_agg, ev_p23, 0);
    aggregate_kernel<<<agrid, 256, 0, s_agg>>>(out, 2);
    cudaEventRecord(ev_done, s_agg);

    // join everything back into the origin stream
    cudaStreamWaitEvent(0, ev_done, 0);
    cudaStreamWaitEvent(0, ev_p23, 0);
}

// round 14
// speedup vs baseline: 1.0087x; 1.0087x over previous
#include <cuda_runtime.h>
#include <cuda_fp16.h>
#include <math_constants.h>
#include <cstdint>

#define B_ 4
#define N_ 20000
#define F_ 256
#define H_ 8
#define D_ 32
#define E_ 320000
#define M_ (B_ * N_)   // 80000 rows in flattened GEMM

// ---------------------------------------------------------------------------
// Scratch
// ---------------------------------------------------------------------------
__device__ __half   g_hp16[(size_t)M_ * F_];        // [B,N,H,D] fp16 (~41MB)
__device__ float    g_asrc[(size_t)M_ * H_];        // [B,N,H]
__device__ float    g_atrg[(size_t)M_ * H_];        // [B,N,H]
__device__ int      g_counts[M_];                   // per (b,n) in-degree
__device__ int      g_offsets[M_];                  // scan; fill bumps to END
__device__ int      g_sorted_src[(size_t)B_ * E_];  // CSR payload: src per slot
__device__ int      g_segsum[64];                   // scan phase partials

#define SCAN_SEGS 10
#define SCAN_SEG_LEN 2000
#define SCAN_PER_THR 8

// ---------------------------------------------------------------------------
// helpers
// ---------------------------------------------------------------------------
__device__ __forceinline__ void mma_fp16(float c[4], uint32_t a0, uint32_t a1,
                                         uint32_t a2, uint32_t a3,
                                         uint32_t b0, uint32_t b1) {
    asm volatile(
        "mma.sync.aligned.m16n8k16.row.col.f32.f16.f16.f32 "
        "{%0,%1,%2,%3},{%4,%5,%6,%7},{%8,%9},{%0,%1,%2,%3};"
        : "+f"(c[0]), "+f"(c[1]), "+f"(c[2]), "+f"(c[3])
        : "r"(a0), "r"(a1), "r"(a2), "r"(a3), "r"(b0), "r"(b1));
}

__device__ __forceinline__ float leaky_exp(float x) {
    x = x > 0.f ? x : 0.2f * x;
    return __expf(x);
}

// ---------------------------------------------------------------------------
// 1) fp16 GEMM (fp32 accum) with DOUBLE-BUFFERED smem (1 sync per k-iter).
//    A[M,256] @ W[256,256]^T -> g_hp16, fused a_src/a_trg projections.
//    128x128x16 tile, 8 warps 2(M)x4(N), warp tile 64x32 (one head per warp).
// ---------------------------------------------------------------------------
#define BK_ 16
#define BKP_ 24
__global__ __launch_bounds__(256) void gemm_fp16_kernel(const float* __restrict__ A,
                                                        const float* __restrict__ W,
                                                        const float* __restrict__ attn_src,
                                                        const float* __restrict__ attn_trg) {
    __shared__ __half As[2][128][BKP_];
    __shared__ __half Bs[2][128][BKP_];

    const int tid   = threadIdx.x;
    const int lane  = tid & 31;
    const int wid   = tid >> 5;
    const int warpM = wid >> 2;
    const int warpN = wid & 3;
    const int bm    = blockIdx.x * 128;
    const int bn    = blockIdx.y * 128;

    const int lr = tid >> 2;        // 0..63
    const int lc = (tid & 3) * 4;   // 0,4,8,12

    float c[4][4][4];
#pragma unroll
    for (int i = 0; i < 4; i++)
#pragma unroll
        for (int j = 0; j < 4; j++)
#pragma unroll
            for (int q = 0; q < 4; q++) c[i][j][q] = 0.f;

    const int r = lane >> 2;   // 0..7
    const int q = lane & 3;    // 0..3

    // preload + store tile 0 into buffer 0
    {
        float4 av0 = *(const float4*)(A + (size_t)(bm + lr) * 256 + lc);
        float4 av1 = *(const float4*)(A + (size_t)(bm + lr + 64) * 256 + lc);
        float4 bv0 = *(const float4*)(W + (size_t)(bn + lr) * 256 + lc);
        float4 bv1 = *(const float4*)(W + (size_t)(bn + lr + 64) * 256 + lc);
        *(__half2*)&As[0][lr][lc]          = __floats2half2_rn(av0.x, av0.y);
        *(__half2*)&As[0][lr][lc + 2]      = __floats2half2_rn(av0.z, av0.w);
        *(__half2*)&As[0][lr + 64][lc]     = __floats2half2_rn(av1.x, av1.y);
        *(__half2*)&As[0][lr + 64][lc + 2] = __floats2half2_rn(av1.z, av1.w);
        *(__half2*)&Bs[0][lr][lc]          = __floats2half2_rn(bv0.x, bv0.y);
        *(__half2*)&Bs[0][lr][lc + 2]      = __floats2half2_rn(bv0.z, bv0.w);
        *(__half2*)&Bs[0][lr + 64][lc]     = __floats2half2_rn(bv1.x, bv1.y);
        *(__half2*)&Bs[0][lr + 64][lc + 2] = __floats2half2_rn(bv1.z, bv1.w);
    }
    __syncthreads();

    int p = 0;
    for (int k0 = 0; k0 < 256; k0 += BK_) {
        const bool has_next = (k0 + BK_ < 256);
        float4 av0, av1, bv0, bv1;
        if (has_next) {   // global prefetch of next tile (overlaps MMAs below)
            av0 = *(const float4*)(A + (size_t)(bm + lr) * 256 + k0 + BK_ + lc);
            av1 = *(const float4*)(A + (size_t)(bm + lr + 64) * 256 + k0 + BK_ + lc);
            bv0 = *(const float4*)(W + (size_t)(bn + lr) * 256 + k0 + BK_ + lc);
            bv1 = *(const float4*)(W + (size_t)(bn + lr + 64) * 256 + k0 + BK_ + lc);
        }

        // compute from buffer p
        uint32_t a[4][4], bf[4][2];
#pragma unroll
        for (int i = 0; i < 4; i++) {
            int row = warpM * 64 + i * 16;
            a[i][0] = *(const uint32_t*)&As[p][row + r][2 * q];
            a[i][1] = *(const uint32_t*)&As[p][row + r + 8][2 * q];
            a[i][2] = *(const uint32_t*)&As[p][row + r][2 * q + 8];
            a[i][3] = *(const uint32_t*)&As[p][row + r + 8][2 * q + 8];
        }
#pragma unroll
        for (int j = 0; j < 4; j++) {
            int col = warpN * 32 + j * 8 + r;
            bf[j][0] = *(const uint32_t*)&Bs[p][col][2 * q];
            bf[j][1] = *(const uint32_t*)&Bs[p][col][2 * q + 8];
        }
#pragma unroll
        for (int i = 0; i < 4; i++)
#pragma unroll
            for (int j = 0; j < 4; j++)
                mma_fp16(c[i][j], a[i][0], a[i][1], a[i][2], a[i][3],
                         bf[j][0], bf[j][1]);

        if (has_next) {   // store next tile into the other buffer, single sync
            const int np = p ^ 1;
            *(__half2*)&As[np][lr][lc]          = __floats2half2_rn(av0.x, av0.y);
            *(__half2*)&As[np][lr][lc + 2]      = __floats2half2_rn(av0.z, av0.w);
            *(__half2*)&As[np][lr + 64][lc]     = __floats2half2_rn(av1.x, av1.y);
            *(__half2*)&As[np][lr + 64][lc + 2] = __floats2half2_rn(av1.z, av1.w);
            *(__half2*)&Bs[np][lr][lc]          = __floats2half2_rn(bv0.x, bv0.y);
            *(__half2*)&Bs[np][lr][lc + 2]      = __floats2half2_rn(bv0.z, bv0.w);
            *(__half2*)&Bs[np][lr + 64][lc]     = __floats2half2_rn(bv1.x, bv1.y);
            *(__half2*)&Bs[np][lr + 64][lc + 2] = __floats2half2_rn(bv1.z, bv1.w);
            __syncthreads();
            p = np;
        }
    }

    // ---- epilogue: fp16 hprime store + fused projections ----
    const int head = (bn >> 5) + warpN;

    float ws[8], wt[8];
#pragma unroll
    for (int j = 0; j < 4; j++) {
        int col = head * 32 + j * 8 + 2 * q;
        ws[2 * j + 0] = __ldg(&attn_src[col]);
        ws[2 * j + 1] = __ldg(&attn_src[col + 1]);
        wt[2 * j + 0] = __ldg(&attn_trg[col]);
        wt[2 * j + 1] = __ldg(&attn_trg[col + 1]);
    }

#pragma unroll
    for (int i = 0; i < 4; i++) {
        int m0 = bm + warpM * 64 + i * 16 + r;
        float s0 = 0.f, s1 = 0.f, t0 = 0.f, t1 = 0.f;
#pragma unroll
        for (int j = 0; j < 4; j++) {
            __half* base = g_hp16 + (size_t)m0 * 256 + bn + warpN * 32 + j * 8 + 2 * q;
            *(__half2*)base = __floats2half2_rn(c[i][j][0], c[i][j][1]);
            *(__half2*)(base + 8 * 256) = __floats2half2_rn(c[i][j][2], c[i][j][3]);
            s0 += c[i][j][0] * ws[2 * j] + c[i][j][1] * ws[2 * j + 1];
            s1 += c[i][j][2] * ws[2 * j] + c[i][j][3] * ws[2 * j + 1];
            t0 += c[i][j][0] * wt[2 * j] + c[i][j][1] * wt[2 * j + 1];
            t1 += c[i][j][2] * wt[2 * j] + c[i][j][3] * wt[2 * j + 1];
        }
#pragma unroll
        for (int o = 1; o < 4; o <<= 1) {
            s0 += __shfl_xor_sync(0xffffffffu, s0, o);
            s1 += __shfl_xor_sync(0xffffffffu, s1, o);
            t0 += __shfl_xor_sync(0xffffffffu, t0, o);
            t1 += __shfl_xor_sync(0xffffffffu, t1, o);
        }
        if (q == 0) {
            g_asrc[(size_t)m0 * H_ + head]       = s0;
            g_asrc[(size_t)(m0 + 8) * H_ + head] = s1;
            g_atrg[(size_t)m0 * H_ + head]       = t0;
            g_atrg[(size_t)(m0 + 8) * H_ + head] = t1;
        }
    }
}

// ---------------------------------------------------------------------------
// 2) histogram of targets
// ---------------------------------------------------------------------------
__global__ __launch_bounds__(256) void hist_kernel(const int* __restrict__ ei) {
    int b = blockIdx.y;
    int e = blockIdx.x * 256 + threadIdx.x;
    if (e < E_) {
        int trg = ei[(size_t)b * 2 * E_ + E_ + e];
        atomicAdd(&g_counts[b * N_ + trg], 1);
    }
}

// ---------------------------------------------------------------------------
// 3) scan, 2-phase
// ---------------------------------------------------------------------------
__global__ __launch_bounds__(256) void scan1_kernel() {
    const int seg  = blockIdx.x;
    const int base = seg * SCAN_SEG_LEN;
    int local = 0;
    for (int i = threadIdx.x; i < SCAN_SEG_LEN; i += 256)
        local += g_counts[base + i];
#pragma unroll
    for (int o = 16; o > 0; o >>= 1) local += __shfl_xor_sync(0xffffffffu, local, o);
    __shared__ int warpsum[8];
    if ((threadIdx.x & 31) == 0) warpsum[threadIdx.x >> 5] = local;
    __syncthreads();
    if (threadIdx.x == 0) {
        int s = 0;
#pragma unroll
        for (int w = 0; w < 8; w++) s += warpsum[w];
        g_segsum[seg] = s;
    }
}

__global__ __launch_bounds__(256) void scan3_kernel() {
    const int seg  = blockIdx.x;
    const int base = seg * SCAN_SEG_LEN;
    const int tid  = threadIdx.x;
    __shared__ int sums[256];
    __shared__ int segbase;

    if (tid == 0) {
        int b = seg / SCAN_SEGS;
        int s = 0;
        for (int k = b * SCAN_SEGS; k < seg; k++) s += g_segsum[k];
        segbase = s;
    }

    int vals[SCAN_PER_THR];
    int tb = tid * SCAN_PER_THR;
    int local = 0;
#pragma unroll
    for (int i = 0; i < SCAN_PER_THR; i++) {
        int idx = tb + i;
        vals[i] = (idx < SCAN_SEG_LEN) ? g_counts[base + idx] : 0;
        local += vals[i];
    }
    int v = local;
    int lane = tid & 31, w = tid >> 5;
#pragma unroll
    for (int o = 1; o < 32; o <<= 1) {
        int u = __shfl_up_sync(0xffffffffu, v, o);
        if (lane >= o) v += u;
    }
    __shared__ int wsum[8];
    if (lane == 31) wsum[w] = v;
    __syncthreads();
    if (tid < 8) {
        int u = wsum[tid];
#pragma unroll
        for (int o = 1; o < 8; o <<= 1) {
            int p = __shfl_up_sync(0xffu, u, o);
            if (tid >= o) u += p;
        }
        sums[tid] = u;
    }
    __syncthreads();
    int prefix = v - local + (w > 0 ? sums[w - 1] : 0) + segbase;
#pragma unroll
    for (int i = 0; i < SCAN_PER_THR; i++) {
        int idx = tb + i;
        if (idx < SCAN_SEG_LEN) {
            g_offsets[base + idx] = prefix;
            prefix += vals[i];
        }
    }
}

// ---------------------------------------------------------------------------
// 4) fill CSR buckets: atomically bump g_offsets itself (post-fill it = END).
// ---------------------------------------------------------------------------
__global__ __launch_bounds__(256) void fill_kernel(const int* __restrict__ ei) {
    int b = blockIdx.y;
    int e = blockIdx.x * 256 + threadIdx.x;
    if (e >= E_) return;
    int src = ei[(size_t)b * 2 * E_ + e];
    int trg = ei[(size_t)b * 2 * E_ + E_ + e];
    int pos = atomicAdd(&g_offsets[b * N_ + trg], 1);
    g_sorted_src[(size_t)b * E_ + pos] = src;
}

// ---------------------------------------------------------------------------
// 5) gather-aggregate: one warp per node, all 8 heads, unroll-4.
// ---------------------------------------------------------------------------
__global__ __launch_bounds__(256) void aggregate_kernel(float* __restrict__ out) {
    const int tid  = threadIdx.x;
    const int wid  = tid >> 5;
    const int lane = tid & 31;
    const int n    = blockIdx.x * 8 + wid;
    const int b    = blockIdx.y;

    __shared__ int   s_src[8][32];
    __shared__ float s_w[8][32][8];

    const int deg = g_counts[b * N_ + n];
    const int off = g_offsets[b * N_ + n] - deg;   // offsets = end after fill

    const float4 at0 = *(const float4*)(g_atrg + (size_t)(b * N_ + n) * H_);
    const float4 at1 = *(const float4*)(g_atrg + (size_t)(b * N_ + n) * H_ + 4);

    const int*    srcs = g_sorted_src + (size_t)b * E_ + off;
    const float*  asb  = g_asrc + (size_t)b * N_ * H_;
    const __half* hpb  = g_hp16 + (size_t)b * N_ * 256;

    const int hgrp = lane >> 3;
    const int dofs = 4 * lane;

    float4 acc0 = make_float4(0.f, 0.f, 0.f, 0.f);
    float4 acc1 = make_float4(0.f, 0.f, 0.f, 0.f);
    float  den0 = 0.f, den1 = 0.f;

    for (int c0 = 0; c0 < deg; c0 += 32) {
        const int cnt = min(32, deg - c0);
        if (lane < cnt) {
            int src = __ldg(srcs + c0 + lane);
            s_src[wid][lane] = src;
            const float4 a0 = *(const float4*)(asb + (size_t)src * H_);
            const float4 a1 = *(const float4*)(asb + (size_t)src * H_ + 4);
            s_w[wid][lane][0] = leaky_exp(a0.x + at0.x);
            s_w[wid][lane][2] = leaky_exp(a0.y + at0.y);
            s_w[wid][lane][4] = leaky_exp(a0.z + at0.z);
            s_w[wid][lane][6] = leaky_exp(a0.w + at0.w);
            s_w[wid][lane][1] = leaky_exp(a1.x + at1.x);
            s_w[wid][lane][3] = leaky_exp(a1.y + at1.y);
            s_w[wid][lane][5] = leaky_exp(a1.z + at1.z);
            s_w[wid][lane][7] = leaky_exp(a1.w + at1.w);
        }
        __syncwarp();

        int j = 0;
        for (; j + 4 <= cnt; j += 4) {
            int   sA = s_src[wid][j],     sB = s_src[wid][j + 1];
            int   sC = s_src[wid][j + 2], sD = s_src[wid][j + 3];
            float2 wA = *(const float2*)&s_w[wid][j][2 * hgrp];
            float2 wB = *(const float2*)&s_w[wid][j + 1][2 * hgrp];
            float2 wC = *(const float2*)&s_w[wid][j + 2][2 * hgrp];
            float2 wD = *(const float2*)&s_w[wid][j + 3][2 * hgrp];
            const __half* rA = hpb + (size_t)sA * 256 + dofs;
            const __half* rB = hpb + (size_t)sB * 256 + dofs;
            const __half* rC = hpb + (size_t)sC * 256 + dofs;
            const __half* rD = hpb + (size_t)sD * 256 + dofs;
            uint2 pA0 = __ldg((const uint2*)rA);
            uint2 pA1 = __ldg((const uint2*)(rA + 128));
            uint2 pB0 = __ldg((const uint2*)rB);
            uint2 pB1 = __ldg((const uint2*)(rB + 128));
            uint2 pC0 = __ldg((const uint2*)rC);
            uint2 pC1 = __ldg((const uint2*)(rC + 128));
            uint2 pD0 = __ldg((const uint2*)rD);
            uint2 pD1 = __ldg((const uint2*)(rD + 128));
            den0 += (wA.x + wB.x) + (wC.x + wD.x);
            den1 += (wA.y + wB.y) + (wC.y + wD.y);
            float2 v0, v1, v2, v3;
            v0 = __half22float2(*(__half2*)&pA0.x); v1 = __half22float2(*(__half2*)&pA0.y);
            v2 = __half22float2(*(__half2*)&pA1.x); v3 = __half22float2(*(__half2*)&pA1.y);
            acc0.x = fmaf(wA.x, v0.x, acc0.x); acc0.y = fmaf(wA.x, v0.y, acc0.y);
            acc0.z = fmaf(wA.x, v1.x, acc0.z); acc0.w = fmaf(wA.x, v1.y, acc0.w);
            acc1.x = fmaf(wA.y, v2.x, acc1.x); acc1.y = fmaf(wA.y, v2.y, acc1.y);
            acc1.z = fmaf(wA.y, v3.x, acc1.z); acc1.w = fmaf(wA.y, v3.y, acc1.w);
            v0 = __half22float2(*(__half2*)&pB0.x); v1 = __half22float2(*(__half2*)&pB0.y);
            v2 = __half22float2(*(__half2*)&pB1.x); v3 = __half22float2(*(__half2*)&pB1.y);
            acc0.x = fmaf(wB.x, v0.x, acc0.x); acc0.y = fmaf(wB.x, v0.y, acc0.y);
            acc0.z = fmaf(wB.x, v1.x, acc0.z); acc0.w = fmaf(wB.x, v1.y, acc0.w);
            acc1.x = fmaf(wB.y, v2.x, acc1.x); acc1.y = fmaf(wB.y, v2.y, acc1.y);
            acc1.z = fmaf(wB.y, v3.x, acc1.z); acc1.w = fmaf(wB.y, v3.y, acc1.w);
            v0 = __half22float2(*(__half2*)&pC0.x); v1 = __half22float2(*(__half2*)&pC0.y);
            v2 = __half22float2(*(__half2*)&pC1.x); v3 = __half22float2(*(__half2*)&pC1.y);
            acc0.x = fmaf(wC.x, v0.x, acc0.x); acc0.y = fmaf(wC.x, v0.y, acc0.y);
            acc0.z = fmaf(wC.x, v1.x, acc0.z); acc0.w = fmaf(wC.x, v1.y, acc0.w);
            acc1.x = fmaf(wC.y, v2.x, acc1.x); acc1.y = fmaf(wC.y, v2.y, acc1.y);
            acc1.z = fmaf(wC.y, v3.x, acc1.z); acc1.w = fmaf(wC.y, v3.y, acc1.w);
            v0 = __half22float2(*(__half2*)&pD0.x); v1 = __half22float2(*(__half2*)&pD0.y);
            v2 = __half22float2(*(__half2*)&pD1.x); v3 = __half22float2(*(__half2*)&pD1.y);
            acc0.x = fmaf(wD.x, v0.x, acc0.x); acc0.y = fmaf(wD.x, v0.y, acc0.y);
            acc0.z = fmaf(wD.x, v1.x, acc0.z); acc0.w = fmaf(wD.x, v1.y, acc0.w);
            acc1.x = fmaf(wD.y, v2.x, acc1.x); acc1.y = fmaf(wD.y, v2.y, acc1.y);
            acc1.z = fmaf(wD.y, v3.x, acc1.z); acc1.w = fmaf(wD.y, v3.y, acc1.w);
        }
        for (; j < cnt; j++) {
            const int s = s_src[wid][j];
            const float2 w = *(const float2*)&s_w[wid][j][2 * hgrp];
            const __half* rr = hpb + (size_t)s * 256 + dofs;
            uint2 p0 = __ldg((const uint2*)rr);
            uint2 p1 = __ldg((const uint2*)(rr + 128));
            den0 += w.x; den1 += w.y;
            float2 a0 = __half22float2(*(__half2*)&p0.x);
            float2 a1 = __half22float2(*(__half2*)&p0.y);
            float2 a2 = __half22float2(*(__half2*)&p1.x);
            float2 a3 = __half22float2(*(__half2*)&p1.y);
            acc0.x = fmaf(w.x, a0.x, acc0.x); acc0.y = fmaf(w.x, a0.y, acc0.y);
            acc0.z = fmaf(w.x, a1.x, acc0.z); acc0.w = fmaf(w.x, a1.y, acc0.w);
            acc1.x = fmaf(w.y, a2.x, acc1.x); acc1.y = fmaf(w.y, a2.y, acc1.y);
            acc1.z = fmaf(w.y, a3.x, acc1.z); acc1.w = fmaf(w.y, a3.y, acc1.w);
        }
        __syncwarp();
    }

    const float i0 = 1.f / (den0 + 1e-16f);
    const float i1 = 1.f / (den1 + 1e-16f);
    const int d0 = 4 * (lane & 7);
    float4* o0 = (float4*)(out + (((size_t)b * H_ + hgrp) * N_ + n) * D_ + d0);
    float4* o1 = (float4*)(out + (((size_t)b * H_ + hgrp + 4) * N_ + n) * D_ + d0);
    *o0 = make_float4(acc0.x * i0, acc0.y * i0, acc0.z * i0, acc0.w * i0);
    *o1 = make_float4(acc1.x * i1, acc1.y * i1, acc1.z * i1, acc1.w * i1);
}

// ---------------------------------------------------------------------------
// kernel_launch — simple 2-stream fork (round-11 schedule, proven best):
//   side: memset(counts) -> hist -> scan1 -> scan3 -> fill
//   main: gemm
//   join -> aggregate
// ---------------------------------------------------------------------------
extern "C" void kernel_launch(void* const* d_in, const int* in_sizes, int n_in,
                              void* d_out, int out_size) {
    const float* h        = (const float*)d_in[0];
    const int*   ei       = (const int*)d_in[1];
    const float* W        = (const float*)d_in[2];
    const float* attn_src = (const float*)d_in[3];
    const float* attn_trg = (const float*)d_in[4];
    float*       out      = (float*)d_out;

    static cudaStream_t s_side = nullptr;
    static cudaEvent_t  ev_fork = nullptr, ev_join = nullptr;
    static void*        counts_ptr = nullptr;
    if (s_side == nullptr) {
        cudaStreamCreateWithFlags(&s_side, cudaStreamNonBlocking);
        cudaEventCreateWithFlags(&ev_fork, cudaEventDisableTiming);
        cudaEventCreateWithFlags(&ev_join, cudaEventDisableTiming);
        cudaGetSymbolAddress(&counts_ptr, g_counts);
    }

    // fork
    cudaEventRecord(ev_fork, 0);
    cudaStreamWaitEvent(s_side, ev_fork, 0);

    // side stream: edge prep
    dim3 egrid((E_ + 255) / 256, B_);
    cudaMemsetAsync(counts_ptr, 0, (size_t)M_ * sizeof(int), s_side);
    hist_kernel<<<egrid, 256, 0, s_side>>>(ei);
    scan1_kernel<<<B_ * SCAN_SEGS, 256, 0, s_side>>>();
    scan3_kernel<<<B_ * SCAN_SEGS, 256, 0, s_side>>>();
    fill_kernel<<<egrid, 256, 0, s_side>>>(ei);
    cudaEventRecord(ev_join, s_side);

    // main stream: GEMM (+ fused projections)
    dim3 ggrid(M_ / 128, 256 / 128);
    gemm_fp16_kernel<<<ggrid, 256>>>(h, W, attn_src, attn_trg);

    // join, then aggregate
    cudaStreamWaitEvent(0, ev_join, 0);
    dim3 agrid(N_ / 8, B_);
    aggregate_kernel<<<agrid, 256>>>(out);
}

// round 15
// speedup vs baseline: 1.0413x; 1.0324x over previous
#include <cuda_runtime.h>
#include <cuda_fp16.h>
#include <math_constants.h>
#include <cstdint>

#define B_ 4
#define N_ 20000
#define F_ 256
#define H_ 8
#define D_ 32
#define E_ 320000
#define M_ (B_ * N_)   // 80000 rows in flattened GEMM

// ---------------------------------------------------------------------------
// Scratch
// ---------------------------------------------------------------------------
__device__ __half   g_hp16[(size_t)M_ * F_];        // [B,N,H,D] fp16 (~41MB)
__device__ float    g_asrc[(size_t)M_ * H_];        // [B,N,H]
__device__ float    g_atrg[(size_t)M_ * H_];        // [B,N,H]
__device__ int      g_counts[M_];                   // per (b,n) in-degree
__device__ int      g_offsets[M_];                  // scan; fill bumps to END
__device__ int      g_sorted_src[(size_t)B_ * E_];  // CSR payload: src per slot
__device__ int      g_segsum[64];                   // scan phase partials

#define SCAN_SEGS 10
#define SCAN_SEG_LEN 2000
#define SCAN_PER_THR 8

// ---------------------------------------------------------------------------
// helpers
// ---------------------------------------------------------------------------
__device__ __forceinline__ void mma_fp16(float c[4], uint32_t a0, uint32_t a1,
                                         uint32_t a2, uint32_t a3,
                                         uint32_t b0, uint32_t b1) {
    asm volatile(
        "mma.sync.aligned.m16n8k16.row.col.f32.f16.f16.f32 "
        "{%0,%1,%2,%3},{%4,%5,%6,%7},{%8,%9},{%0,%1,%2,%3};"
        : "+f"(c[0]), "+f"(c[1]), "+f"(c[2]), "+f"(c[3])
        : "r"(a0), "r"(a1), "r"(a2), "r"(a3), "r"(b0), "r"(b1));
}

__device__ __forceinline__ void ldsm_x4(uint32_t& r0, uint32_t& r1,
                                        uint32_t& r2, uint32_t& r3, uint32_t addr) {
    asm volatile("ldmatrix.sync.aligned.m8n8.x4.shared.b16 {%0,%1,%2,%3}, [%4];"
                 : "=r"(r0), "=r"(r1), "=r"(r2), "=r"(r3) : "r"(addr));
}

__device__ __forceinline__ void ldsm_x2(uint32_t& r0, uint32_t& r1, uint32_t addr) {
    asm volatile("ldmatrix.sync.aligned.m8n8.x2.shared.b16 {%0,%1}, [%2];"
                 : "=r"(r0), "=r"(r1) : "r"(addr));
}

__device__ __forceinline__ float leaky_exp(float x) {
    x = x > 0.f ? x : 0.2f * x;
    return __expf(x);
}

// ---------------------------------------------------------------------------
// 0) init: zero counts only
// ---------------------------------------------------------------------------
__global__ void init_kernel() {
    int i = blockIdx.x * blockDim.x + threadIdx.x;
    if (i < M_) g_counts[i] = 0;
}

// ---------------------------------------------------------------------------
// 1) fp16 GEMM (fp32 accum): A[M,256] @ W[256,256]^T -> g_hp16, fused a_src/a_trg.
//    128x128x16 tile, 8 warps 2(M)x4(N), warp tile 64x32 (one head per warp).
//    Fragment loads via ldmatrix (8 LDSM vs 24 LDS.32 per warp-iter).
// ---------------------------------------------------------------------------
#define BK_ 16
#define BKP_ 24
__global__ __launch_bounds__(256) void gemm_fp16_kernel(const float* __restrict__ A,
                                                        const float* __restrict__ W,
                                                        const float* __restrict__ attn_src,
                                                        const float* __restrict__ attn_trg) {
    __shared__ __half As[128][BKP_];
    __shared__ __half Bs[128][BKP_];

    const int tid   = threadIdx.x;
    const int lane  = tid & 31;
    const int wid   = tid >> 5;
    const int warpM = wid >> 2;
    const int warpN = wid & 3;
    const int bm    = blockIdx.x * 128;
    const int bn    = blockIdx.y * 128;

    const int lr = tid >> 2;
    const int lc = (tid & 3) * 4;

    float c[4][4][4];
#pragma unroll
    for (int i = 0; i < 4; i++)
#pragma unroll
        for (int j = 0; j < 4; j++)
#pragma unroll
            for (int q = 0; q < 4; q++) c[i][j][q] = 0.f;

    float4 av0 = *(const float4*)(A + (size_t)(bm + lr) * 256 + lc);
    float4 av1 = *(const float4*)(A + (size_t)(bm + lr + 64) * 256 + lc);
    float4 bv0 = *(const float4*)(W + (size_t)(bn + lr) * 256 + lc);
    float4 bv1 = *(const float4*)(W + (size_t)(bn + lr + 64) * 256 + lc);

    const int r = lane >> 2;
    const int q = lane & 3;

    // loop-invariant ldmatrix per-lane addresses
    // A x4: lanes [0..7]=rows0-7@k0, [8..15]=rows8-15@k0, [16..23]=rows0-7@k8, [24..31]=rows8-15@k8
    const uint32_t sA = (uint32_t)__cvta_generic_to_shared(&As[0][0]);
    const uint32_t sB = (uint32_t)__cvta_generic_to_shared(&Bs[0][0]);
    const int aRowOff = (lane & 7) + ((lane >> 3) & 1) * 8;
    const int aColOff = (lane >> 4) * 8;
    uint32_t aAddr[4];
#pragma unroll
    for (int i = 0; i < 4; i++)
        aAddr[i] = sA + (uint32_t)(((warpM * 64 + i * 16 + aRowOff) * BKP_ + aColOff) * 2);
    // B x2: lanes [0..7]=n0-7@k0, [8..15]=n0-7@k8 (lanes>=16 unused)
    const int bRowOff = lane & 7;
    const int bColOff = ((lane >> 3) & 1) * 8;
    uint32_t bAddr[4];
#pragma unroll
    for (int j = 0; j < 4; j++)
        bAddr[j] = sB + (uint32_t)(((warpN * 32 + j * 8 + bRowOff) * BKP_ + bColOff) * 2);

    for (int k0 = 0; k0 < 256; k0 += BK_) {
        *(__half2*)&As[lr][lc]          = __floats2half2_rn(av0.x, av0.y);
        *(__half2*)&As[lr][lc + 2]      = __floats2half2_rn(av0.z, av0.w);
        *(__half2*)&As[lr + 64][lc]     = __floats2half2_rn(av1.x, av1.y);
        *(__half2*)&As[lr + 64][lc + 2] = __floats2half2_rn(av1.z, av1.w);
        *(__half2*)&Bs[lr][lc]          = __floats2half2_rn(bv0.x, bv0.y);
        *(__half2*)&Bs[lr][lc + 2]      = __floats2half2_rn(bv0.z, bv0.w);
        *(__half2*)&Bs[lr + 64][lc]     = __floats2half2_rn(bv1.x, bv1.y);
        *(__half2*)&Bs[lr + 64][lc + 2] = __floats2half2_rn(bv1.z, bv1.w);
        __syncthreads();

        if (k0 + BK_ < 256) {
            av0 = *(const float4*)(A + (size_t)(bm + lr) * 256 + k0 + BK_ + lc);
            av1 = *(const float4*)(A + (size_t)(bm + lr + 64) * 256 + k0 + BK_ + lc);
            bv0 = *(const float4*)(W + (size_t)(bn + lr) * 256 + k0 + BK_ + lc);
            bv1 = *(const float4*)(W + (size_t)(bn + lr + 64) * 256 + k0 + BK_ + lc);
        }

        uint32_t a[4][4], bf[4][2];
#pragma unroll
        for (int i = 0; i < 4; i++)
            ldsm_x4(a[i][0], a[i][1], a[i][2], a[i][3], aAddr[i]);
#pragma unroll
        for (int j = 0; j < 4; j++)
            ldsm_x2(bf[j][0], bf[j][1], bAddr[j]);
#pragma unroll
        for (int i = 0; i < 4; i++)
#pragma unroll
            for (int j = 0; j < 4; j++)
                mma_fp16(c[i][j], a[i][0], a[i][1], a[i][2], a[i][3],
                         bf[j][0], bf[j][1]);
        __syncthreads();
    }

    const int head = (bn >> 5) + warpN;

    float ws[8], wt[8];
#pragma unroll
    for (int j = 0; j < 4; j++) {
        int col = head * 32 + j * 8 + 2 * q;
        ws[2 * j + 0] = __ldg(&attn_src[col]);
        ws[2 * j + 1] = __ldg(&attn_src[col + 1]);
        wt[2 * j + 0] = __ldg(&attn_trg[col]);
        wt[2 * j + 1] = __ldg(&attn_trg[col + 1]);
    }

#pragma unroll
    for (int i = 0; i < 4; i++) {
        int m0 = bm + warpM * 64 + i * 16 + r;
        float s0 = 0.f, s1 = 0.f, t0 = 0.f, t1 = 0.f;
#pragma unroll
        for (int j = 0; j < 4; j++) {
            __half* base = g_hp16 + (size_t)m0 * 256 + bn + warpN * 32 + j * 8 + 2 * q;
            *(__half2*)base = __floats2half2_rn(c[i][j][0], c[i][j][1]);
            *(__half2*)(base + 8 * 256) = __floats2half2_rn(c[i][j][2], c[i][j][3]);
            s0 += c[i][j][0] * ws[2 * j] + c[i][j][1] * ws[2 * j + 1];
            s1 += c[i][j][2] * ws[2 * j] + c[i][j][3] * ws[2 * j + 1];
            t0 += c[i][j][0] * wt[2 * j] + c[i][j][1] * wt[2 * j + 1];
            t1 += c[i][j][2] * wt[2 * j] + c[i][j][3] * wt[2 * j + 1];
        }
#pragma unroll
        for (int o = 1; o < 4; o <<= 1) {
            s0 += __shfl_xor_sync(0xffffffffu, s0, o);
            s1 += __shfl_xor_sync(0xffffffffu, s1, o);
            t0 += __shfl_xor_sync(0xffffffffu, t0, o);
            t1 += __shfl_xor_sync(0xffffffffu, t1, o);
        }
        if (q == 0) {
            g_asrc[(size_t)m0 * H_ + head]       = s0;
            g_asrc[(size_t)(m0 + 8) * H_ + head] = s1;
            g_atrg[(size_t)m0 * H_ + head]       = t0;
            g_atrg[(size_t)(m0 + 8) * H_ + head] = t1;
        }
    }
}

// ---------------------------------------------------------------------------
// 2) histogram of targets
// ---------------------------------------------------------------------------
__global__ __launch_bounds__(256) void hist_kernel(const int* __restrict__ ei) {
    int b = blockIdx.y;
    int e = blockIdx.x * 256 + threadIdx.x;
    if (e < E_) {
        int trg = ei[(size_t)b * 2 * E_ + E_ + e];
        atomicAdd(&g_counts[b * N_ + trg], 1);
    }
}

// ---------------------------------------------------------------------------
// 3) scan, 2-phase
// ---------------------------------------------------------------------------
__global__ __launch_bounds__(256) void scan1_kernel() {
    const int seg  = blockIdx.x;
    const int base = seg * SCAN_SEG_LEN;
    int local = 0;
    for (int i = threadIdx.x; i < SCAN_SEG_LEN; i += 256)
        local += g_counts[base + i];
#pragma unroll
    for (int o = 16; o > 0; o >>= 1) local += __shfl_xor_sync(0xffffffffu, local, o);
    __shared__ int warpsum[8];
    if ((threadIdx.x & 31) == 0) warpsum[threadIdx.x >> 5] = local;
    __syncthreads();
    if (threadIdx.x == 0) {
        int s = 0;
#pragma unroll
        for (int w = 0; w < 8; w++) s += warpsum[w];
        g_segsum[seg] = s;
    }
}

__global__ __launch_bounds__(256) void scan3_kernel() {
    const int seg  = blockIdx.x;
    const int base = seg * SCAN_SEG_LEN;
    const int tid  = threadIdx.x;
    __shared__ int sums[256];
    __shared__ int segbase;

    if (tid == 0) {
        int b = seg / SCAN_SEGS;
        int s = 0;
        for (int k = b * SCAN_SEGS; k < seg; k++) s += g_segsum[k];
        segbase = s;
    }

    int vals[SCAN_PER_THR];
    int tb = tid * SCAN_PER_THR;
    int local = 0;
#pragma unroll
    for (int i = 0; i < SCAN_PER_THR; i++) {
        int idx = tb + i;
        vals[i] = (idx < SCAN_SEG_LEN) ? g_counts[base + idx] : 0;
        local += vals[i];
    }
    int v = local;
    int lane = tid & 31, w = tid >> 5;
#pragma unroll
    for (int o = 1; o < 32; o <<= 1) {
        int u = __shfl_up_sync(0xffffffffu, v, o);
        if (lane >= o) v += u;
    }
    __shared__ int wsum[8];
    if (lane == 31) wsum[w] = v;
    __syncthreads();
    if (tid < 8) {
        int u = wsum[tid];
#pragma unroll
        for (int o = 1; o < 8; o <<= 1) {
            int p = __shfl_up_sync(0xffu, u, o);
            if (tid >= o) u += p;
        }
        sums[tid] = u;
    }
    __syncthreads();
    int prefix = v - local + (w > 0 ? sums[w - 1] : 0) + segbase;
#pragma unroll
    for (int i = 0; i < SCAN_PER_THR; i++) {
        int idx = tb + i;
        if (idx < SCAN_SEG_LEN) {
            g_offsets[base + idx] = prefix;
            prefix += vals[i];
        }
    }
}

// ---------------------------------------------------------------------------
// 4) fill CSR buckets: atomically bump g_offsets itself (post-fill it = END).
// ---------------------------------------------------------------------------
__global__ __launch_bounds__(256) void fill_kernel(const int* __restrict__ ei) {
    int b = blockIdx.y;
    int e = blockIdx.x * 256 + threadIdx.x;
    if (e >= E_) return;
    int src = ei[(size_t)b * 2 * E_ + e];
    int trg = ei[(size_t)b * 2 * E_ + E_ + e];
    int pos = atomicAdd(&g_offsets[b * N_ + trg], 1);
    g_sorted_src[(size_t)b * E_ + pos] = src;
}

// ---------------------------------------------------------------------------
// 5) gather-aggregate: one warp per node, all 8 heads, unroll-4.
// ---------------------------------------------------------------------------
__global__ __launch_bounds__(256) void aggregate_kernel(float* __restrict__ out) {
    const int tid  = threadIdx.x;
    const int wid  = tid >> 5;
    const int lane = tid & 31;
    const int n    = blockIdx.x * 8 + wid;
    const int b    = blockIdx.y;

    __shared__ int   s_src[8][32];
    __shared__ float s_w[8][32][8];

    const int deg = g_counts[b * N_ + n];
    const int off = g_offsets[b * N_ + n] - deg;   // offsets = end after fill

    const float4 at0 = *(const float4*)(g_atrg + (size_t)(b * N_ + n) * H_);
    const float4 at1 = *(const float4*)(g_atrg + (size_t)(b * N_ + n) * H_ + 4);

    const int*    srcs = g_sorted_src + (size_t)b * E_ + off;
    const float*  asb  = g_asrc + (size_t)b * N_ * H_;
    const __half* hpb  = g_hp16 + (size_t)b * N_ * 256;

    const int hgrp = lane >> 3;
    const int dofs = 4 * lane;

    float4 acc0 = make_float4(0.f, 0.f, 0.f, 0.f);
    float4 acc1 = make_float4(0.f, 0.f, 0.f, 0.f);
    float  den0 = 0.f, den1 = 0.f;

    for (int c0 = 0; c0 < deg; c0 += 32) {
        const int cnt = min(32, deg - c0);
        if (lane < cnt) {
            int src = __ldg(srcs + c0 + lane);
            s_src[wid][lane] = src;
            const float4 a0 = *(const float4*)(asb + (size_t)src * H_);
            const float4 a1 = *(const float4*)(asb + (size_t)src * H_ + 4);
            s_w[wid][lane][0] = leaky_exp(a0.x + at0.x);
            s_w[wid][lane][2] = leaky_exp(a0.y + at0.y);
            s_w[wid][lane][4] = leaky_exp(a0.z + at0.z);
            s_w[wid][lane][6] = leaky_exp(a0.w + at0.w);
            s_w[wid][lane][1] = leaky_exp(a1.x + at1.x);
            s_w[wid][lane][3] = leaky_exp(a1.y + at1.y);
            s_w[wid][lane][5] = leaky_exp(a1.z + at1.z);
            s_w[wid][lane][7] = leaky_exp(a1.w + at1.w);
        }
        __syncwarp();

        int j = 0;
        for (; j + 4 <= cnt; j += 4) {
            int   sA = s_src[wid][j],     sB = s_src[wid][j + 1];
            int   sC = s_src[wid][j + 2], sD = s_src[wid][j + 3];
            float2 wA = *(const float2*)&s_w[wid][j][2 * hgrp];
            float2 wB = *(const float2*)&s_w[wid][j + 1][2 * hgrp];
            float2 wC = *(const float2*)&s_w[wid][j + 2][2 * hgrp];
            float2 wD = *(const float2*)&s_w[wid][j + 3][2 * hgrp];
            const __half* rA = hpb + (size_t)sA * 256 + dofs;
            const __half* rB = hpb + (size_t)sB * 256 + dofs;
            const __half* rC = hpb + (size_t)sC * 256 + dofs;
            const __half* rD = hpb + (size_t)sD * 256 + dofs;
            uint2 pA0 = __ldg((const uint2*)rA);
            uint2 pA1 = __ldg((const uint2*)(rA + 128));
            uint2 pB0 = __ldg((const uint2*)rB);
            uint2 pB1 = __ldg((const uint2*)(rB + 128));
            uint2 pC0 = __ldg((const uint2*)rC);
            uint2 pC1 = __ldg((const uint2*)(rC + 128));
            uint2 pD0 = __ldg((const uint2*)rD);
            uint2 pD1 = __ldg((const uint2*)(rD + 128));
            den0 += (wA.x + wB.x) + (wC.x + wD.x);
            den1 += (wA.y + wB.y) + (wC.y + wD.y);
            float2 v0, v1, v2, v3;
            v0 = __half22float2(*(__half2*)&pA0.x); v1 = __half22float2(*(__half2*)&pA0.y);
            v2 = __half22float2(*(__half2*)&pA1.x); v3 = __half22float2(*(__half2*)&pA1.y);
            acc0.x = fmaf(wA.x, v0.x, acc0.x); acc0.y = fmaf(wA.x, v0.y, acc0.y);
            acc0.z = fmaf(wA.x, v1.x, acc0.z); acc0.w = fmaf(wA.x, v1.y, acc0.w);
            acc1.x = fmaf(wA.y, v2.x, acc1.x); acc1.y = fmaf(wA.y, v2.y, acc1.y);
            acc1.z = fmaf(wA.y, v3.x, acc1.z); acc1.w = fmaf(wA.y, v3.y, acc1.w);
            v0 = __half22float2(*(__half2*)&pB0.x); v1 = __half22float2(*(__half2*)&pB0.y);
            v2 = __half22float2(*(__half2*)&pB1.x); v3 = __half22float2(*(__half2*)&pB1.y);
            acc0.x = fmaf(wB.x, v0.x, acc0.x); acc0.y = fmaf(wB.x, v0.y, acc0.y);
            acc0.z = fmaf(wB.x, v1.x, acc0.z); acc0.w = fmaf(wB.x, v1.y, acc0.w);
            acc1.x = fmaf(wB.y, v2.x, acc1.x); acc1.y = fmaf(wB.y, v2.y, acc1.y);
            acc1.z = fmaf(wB.y, v3.x, acc1.z); acc1.w = fmaf(wB.y, v3.y, acc1.w);
            v0 = __half22float2(*(__half2*)&pC0.x); v1 = __half22float2(*(__half2*)&pC0.y);
            v2 = __half22float2(*(__half2*)&pC1.x); v3 = __half22float2(*(__half2*)&pC1.y);
            acc0.x = fmaf(wC.x, v0.x, acc0.x); acc0.y = fmaf(wC.x, v0.y, acc0.y);
            acc0.z = fmaf(wC.x, v1.x, acc0.z); acc0.w = fmaf(wC.x, v1.y, acc0.w);
            acc1.x = fmaf(wC.y, v2.x, acc1.x); acc1.y = fmaf(wC.y, v2.y, acc1.y);
            acc1.z = fmaf(wC.y, v3.x, acc1.z); acc1.w = fmaf(wC.y, v3.y, acc1.w);
            v0 = __half22float2(*(__half2*)&pD0.x); v1 = __half22float2(*(__half2*)&pD0.y);
            v2 = __half22float2(*(__half2*)&pD1.x); v3 = __half22float2(*(__half2*)&pD1.y);
            acc0.x = fmaf(wD.x, v0.x, acc0.x); acc0.y = fmaf(wD.x, v0.y, acc0.y);
            acc0.z = fmaf(wD.x, v1.x, acc0.z); acc0.w = fmaf(wD.x, v1.y, acc0.w);
            acc1.x = fmaf(wD.y, v2.x, acc1.x); acc1.y = fmaf(wD.y, v2.y, acc1.y);
            acc1.z = fmaf(wD.y, v3.x, acc1.z); acc1.w = fmaf(wD.y, v3.y, acc1.w);
        }
        for (; j < cnt; j++) {
            const int s = s_src[wid][j];
            const float2 w = *(const float2*)&s_w[wid][j][2 * hgrp];
            const __half* rr = hpb + (size_t)s * 256 + dofs;
            uint2 p0 = __ldg((const uint2*)rr);
            uint2 p1 = __ldg((const uint2*)(rr + 128));
            den0 += w.x; den1 += w.y;
            float2 a0 = __half22float2(*(__half2*)&p0.x);
            float2 a1 = __half22float2(*(__half2*)&p0.y);
            float2 a2 = __half22float2(*(__half2*)&p1.x);
            float2 a3 = __half22float2(*(__half2*)&p1.y);
            acc0.x = fmaf(w.x, a0.x, acc0.x); acc0.y = fmaf(w.x, a0.y, acc0.y);
            acc0.z = fmaf(w.x, a1.x, acc0.z); acc0.w = fmaf(w.x, a1.y, acc0.w);
            acc1.x = fmaf(w.y, a2.x, acc1.x); acc1.y = fmaf(w.y, a2.y, acc1.y);
            acc1.z = fmaf(w.y, a3.x, acc1.z); acc1.w = fmaf(w.y, a3.y, acc1.w);
        }
        __syncwarp();
    }

    const float i0 = 1.f / (den0 + 1e-16f);
    const float i1 = 1.f / (den1 + 1e-16f);
    const int d0 = 4 * (lane & 7);
    float4* o0 = (float4*)(out + (((size_t)b * H_ + hgrp) * N_ + n) * D_ + d0);
    float4* o1 = (float4*)(out + (((size_t)b * H_ + hgrp + 4) * N_ + n) * D_ + d0);
    *o0 = make_float4(acc0.x * i0, acc0.y * i0, acc0.z * i0, acc0.w * i0);
    *o1 = make_float4(acc1.x * i1, acc1.y * i1, acc1.z * i1, acc1.w * i1);
}

// ---------------------------------------------------------------------------
// kernel_launch — simple 2-stream fork (round-11 schedule, proven best).
// ---------------------------------------------------------------------------
extern "C" void kernel_launch(void* const* d_in, const int* in_sizes, int n_in,
                              void* d_out, int out_size) {
    const float* h        = (const float*)d_in[0];
    const int*   ei       = (const int*)d_in[1];
    const float* W        = (const float*)d_in[2];
    const float* attn_src = (const float*)d_in[3];
    const float* attn_trg = (const float*)d_in[4];
    float*       out      = (float*)d_out;

    static cudaStream_t s_side = nullptr;
    static cudaEvent_t  ev_fork = nullptr, ev_join = nullptr;
    if (s_side == nullptr) {
        cudaStreamCreateWithFlags(&s_side, cudaStreamNonBlocking);
        cudaEventCreateWithFlags(&ev_fork, cudaEventDisableTiming);
        cudaEventCreateWithFlags(&ev_join, cudaEventDisableTiming);
    }

    // fork
    cudaEventRecord(ev_fork, 0);
    cudaStreamWaitEvent(s_side, ev_fork, 0);

    // side stream: edge prep
    dim3 egrid((E_ + 255) / 256, B_);
    init_kernel<<<(M_ + 255) / 256, 256, 0, s_side>>>();
    hist_kernel<<<egrid, 256, 0, s_side>>>(ei);
    scan1_kernel<<<B_ * SCAN_SEGS, 256, 0, s_side>>>();
    scan3_kernel<<<B_ * SCAN_SEGS, 256, 0, s_side>>>();
    fill_kernel<<<egrid, 256, 0, s_side>>>(ei);
    cudaEventRecord(ev_join, s_side);

    // main stream: GEMM (+ fused projections)
    dim3 ggrid(M_ / 128, 256 / 128);
    gemm_fp16_kernel<<<ggrid, 256>>>(h, W, attn_src, attn_trg);

    // join, then aggregate
    cudaStreamWaitEvent(0, ev_join, 0);
    dim3 agrid(N_ / 8, B_);
    aggregate_kernel<<<agrid, 256>>>(out);
}

// round 16
// speedup vs baseline: 1.0853x; 1.0422x over previous
#include <cuda_runtime.h>
#include <cuda_fp16.h>
#include <math_constants.h>
#include <cstdint>

#define B_ 4
#define N_ 20000
#define F_ 256
#define H_ 8
#define D_ 32
#define E_ 320000
#define M_ (B_ * N_)   // 80000 rows in flattened GEMM

// ---------------------------------------------------------------------------
// Scratch
// ---------------------------------------------------------------------------
__device__ __half   g_hp16[(size_t)M_ * F_];        // [B,N,H,D] fp16 (~41MB)
__device__ float    g_asrc[(size_t)M_ * H_];        // [B,N,H]
__device__ float    g_atrg[(size_t)M_ * H_];        // [B,N,H]
__device__ int      g_counts[M_];                   // per (b,n) in-degree
__device__ int      g_offsets[M_];                  // scan; fill bumps to END
__device__ int      g_sorted_src[(size_t)B_ * E_];  // CSR payload: src per slot
__device__ int      g_segsum[64];                   // scan phase partials

#define SCAN_SEGS 10
#define SCAN_SEG_LEN 2000
#define SCAN_PER_THR 8

// ---------------------------------------------------------------------------
// helpers
// ---------------------------------------------------------------------------
__device__ __forceinline__ void mma_fp16(float c[4], uint32_t a0, uint32_t a1,
                                         uint32_t a2, uint32_t a3,
                                         uint32_t b0, uint32_t b1) {
    asm volatile(
        "mma.sync.aligned.m16n8k16.row.col.f32.f16.f16.f32 "
        "{%0,%1,%2,%3},{%4,%5,%6,%7},{%8,%9},{%0,%1,%2,%3};"
        : "+f"(c[0]), "+f"(c[1]), "+f"(c[2]), "+f"(c[3])
        : "r"(a0), "r"(a1), "r"(a2), "r"(a3), "r"(b0), "r"(b1));
}

__device__ __forceinline__ void ldsm_x4(uint32_t& r0, uint32_t& r1,
                                        uint32_t& r2, uint32_t& r3, uint32_t addr) {
    asm volatile("ldmatrix.sync.aligned.m8n8.x4.shared.b16 {%0,%1,%2,%3}, [%4];"
                 : "=r"(r0), "=r"(r1), "=r"(r2), "=r"(r3) : "r"(addr));
}

__device__ __forceinline__ void ldsm_x2(uint32_t& r0, uint32_t& r1, uint32_t addr) {
    asm volatile("ldmatrix.sync.aligned.m8n8.x2.shared.b16 {%0,%1}, [%2];"
                 : "=r"(r0), "=r"(r1) : "r"(addr));
}

__device__ __forceinline__ float leaky_exp(float x) {
    x = x > 0.f ? x : 0.2f * x;
    return __expf(x);
}

// ---------------------------------------------------------------------------
// 0) init: zero counts only
// ---------------------------------------------------------------------------
__global__ void init_kernel() {
    int i = blockIdx.x * blockDim.x + threadIdx.x;
    if (i < M_) g_counts[i] = 0;
}

// ---------------------------------------------------------------------------
// 1) fp16 GEMM (fp32 accum): A[M,256] @ W[256,256]^T -> g_hp16, fused a_src/a_trg.
//    128x128x32 tile (8 k-iters, 16 syncs total), 8 warps 2(M)x4(N),
//    warp tile 64x32 (one head per warp). ldmatrix fragment loads.
// ---------------------------------------------------------------------------
#define BK_ 32
#define BKP_ 40   // padded row in halves: stride 20 words -> conflict-free LDSM
__global__ __launch_bounds__(256) void gemm_fp16_kernel(const float* __restrict__ A,
                                                        const float* __restrict__ W,
                                                        const float* __restrict__ attn_src,
                                                        const float* __restrict__ attn_trg) {
    __shared__ __half As[128][BKP_];
    __shared__ __half Bs[128][BKP_];

    const int tid   = threadIdx.x;
    const int lane  = tid & 31;
    const int wid   = tid >> 5;
    const int warpM = wid >> 2;
    const int warpN = wid & 3;
    const int bm    = blockIdx.x * 128;
    const int bn    = blockIdx.y * 128;

    // tile loader mapping: rows (tid>>3)+{0,32,64,96}, cols (tid&7)*4 within BK
    const int ldr = tid >> 3;          // 0..31
    const int ldc = (tid & 7) * 4;     // 0,4,...,28

    float c[4][4][4];
#pragma unroll
    for (int i = 0; i < 4; i++)
#pragma unroll
        for (int j = 0; j < 4; j++)
#pragma unroll
            for (int q = 0; q < 4; q++) c[i][j][q] = 0.f;

    const int r = lane >> 2;
    const int q = lane & 3;

    // prefetch tile 0
    float4 av[4], bv[4];
#pragma unroll
    for (int m = 0; m < 4; m++) {
        av[m] = *(const float4*)(A + (size_t)(bm + ldr + 32 * m) * 256 + ldc);
        bv[m] = *(const float4*)(W + (size_t)(bn + ldr + 32 * m) * 256 + ldc);
    }

    // loop-invariant ldmatrix per-lane addresses
    const uint32_t sA = (uint32_t)__cvta_generic_to_shared(&As[0][0]);
    const uint32_t sB = (uint32_t)__cvta_generic_to_shared(&Bs[0][0]);
    const int aRowOff = (lane & 7) + ((lane >> 3) & 1) * 8;
    const int aColOff = (lane >> 4) * 8;
    uint32_t aAddr[4];
#pragma unroll
    for (int i = 0; i < 4; i++)
        aAddr[i] = sA + (uint32_t)(((warpM * 64 + i * 16 + aRowOff) * BKP_ + aColOff) * 2);
    const int bRowOff = lane & 7;
    const int bColOff = ((lane >> 3) & 1) * 8;
    uint32_t bAddr[4];
#pragma unroll
    for (int j = 0; j < 4; j++)
        bAddr[j] = sB + (uint32_t)(((warpN * 32 + j * 8 + bRowOff) * BKP_ + bColOff) * 2);

    for (int k0 = 0; k0 < 256; k0 += BK_) {
        // store current tile (fp16 convert)
#pragma unroll
        for (int m = 0; m < 4; m++) {
            int row = ldr + 32 * m;
            *(__half2*)&As[row][ldc]     = __floats2half2_rn(av[m].x, av[m].y);
            *(__half2*)&As[row][ldc + 2] = __floats2half2_rn(av[m].z, av[m].w);
            *(__half2*)&Bs[row][ldc]     = __floats2half2_rn(bv[m].x, bv[m].y);
            *(__half2*)&Bs[row][ldc + 2] = __floats2half2_rn(bv[m].z, bv[m].w);
        }
        __syncthreads();

        if (k0 + BK_ < 256) {   // prefetch next tile (overlaps MMAs)
#pragma unroll
            for (int m = 0; m < 4; m++) {
                av[m] = *(const float4*)(A + (size_t)(bm + ldr + 32 * m) * 256 + k0 + BK_ + ldc);
                bv[m] = *(const float4*)(W + (size_t)(bn + ldr + 32 * m) * 256 + k0 + BK_ + ldc);
            }
        }

#pragma unroll
        for (int ks = 0; ks < BK_; ks += 16) {
            uint32_t a[4][4], bf[4][2];
#pragma unroll
            for (int i = 0; i < 4; i++)
                ldsm_x4(a[i][0], a[i][1], a[i][2], a[i][3], aAddr[i] + ks * 2);
#pragma unroll
            for (int j = 0; j < 4; j++)
                ldsm_x2(bf[j][0], bf[j][1], bAddr[j] + ks * 2);
#pragma unroll
            for (int i = 0; i < 4; i++)
#pragma unroll
                for (int j = 0; j < 4; j++)
                    mma_fp16(c[i][j], a[i][0], a[i][1], a[i][2], a[i][3],
                             bf[j][0], bf[j][1]);
        }
        __syncthreads();
    }

    // ---- epilogue: fp16 hprime store + fused projections ----
    const int head = (bn >> 5) + warpN;

    float ws[8], wt[8];
#pragma unroll
    for (int j = 0; j < 4; j++) {
        int col = head * 32 + j * 8 + 2 * q;
        ws[2 * j + 0] = __ldg(&attn_src[col]);
        ws[2 * j + 1] = __ldg(&attn_src[col + 1]);
        wt[2 * j + 0] = __ldg(&attn_trg[col]);
        wt[2 * j + 1] = __ldg(&attn_trg[col + 1]);
    }

#pragma unroll
    for (int i = 0; i < 4; i++) {
        int m0 = bm + warpM * 64 + i * 16 + r;
        float s0 = 0.f, s1 = 0.f, t0 = 0.f, t1 = 0.f;
#pragma unroll
        for (int j = 0; j < 4; j++) {
            __half* base = g_hp16 + (size_t)m0 * 256 + bn + warpN * 32 + j * 8 + 2 * q;
            *(__half2*)base = __floats2half2_rn(c[i][j][0], c[i][j][1]);
            *(__half2*)(base + 8 * 256) = __floats2half2_rn(c[i][j][2], c[i][j][3]);
            s0 += c[i][j][0] * ws[2 * j] + c[i][j][1] * ws[2 * j + 1];
            s1 += c[i][j][2] * ws[2 * j] + c[i][j][3] * ws[2 * j + 1];
            t0 += c[i][j][0] * wt[2 * j] + c[i][j][1] * wt[2 * j + 1];
            t1 += c[i][j][2] * wt[2 * j] + c[i][j][3] * wt[2 * j + 1];
        }
#pragma unroll
        for (int o = 1; o < 4; o <<= 1) {
            s0 += __shfl_xor_sync(0xffffffffu, s0, o);
            s1 += __shfl_xor_sync(0xffffffffu, s1, o);
            t0 += __shfl_xor_sync(0xffffffffu, t0, o);
            t1 += __shfl_xor_sync(0xffffffffu, t1, o);
        }
        if (q == 0) {
            g_asrc[(size_t)m0 * H_ + head]       = s0;
            g_asrc[(size_t)(m0 + 8) * H_ + head] = s1;
            g_atrg[(size_t)m0 * H_ + head]       = t0;
            g_atrg[(size_t)(m0 + 8) * H_ + head] = t1;
        }
    }
}

// ---------------------------------------------------------------------------
// 2) histogram of targets
// ---------------------------------------------------------------------------
__global__ __launch_bounds__(256) void hist_kernel(const int* __restrict__ ei) {
    int b = blockIdx.y;
    int e = blockIdx.x * 256 + threadIdx.x;
    if (e < E_) {
        int trg = ei[(size_t)b * 2 * E_ + E_ + e];
        atomicAdd(&g_counts[b * N_ + trg], 1);
    }
}

// ---------------------------------------------------------------------------
// 3) scan, 2-phase
// ---------------------------------------------------------------------------
__global__ __launch_bounds__(256) void scan1_kernel() {
    const int seg  = blockIdx.x;
    const int base = seg * SCAN_SEG_LEN;
    int local = 0;
    for (int i = threadIdx.x; i < SCAN_SEG_LEN; i += 256)
        local += g_counts[base + i];
#pragma unroll
    for (int o = 16; o > 0; o >>= 1) local += __shfl_xor_sync(0xffffffffu, local, o);
    __shared__ int warpsum[8];
    if ((threadIdx.x & 31) == 0) warpsum[threadIdx.x >> 5] = local;
    __syncthreads();
    if (threadIdx.x == 0) {
        int s = 0;
#pragma unroll
        for (int w = 0; w < 8; w++) s += warpsum[w];
        g_segsum[seg] = s;
    }
}

__global__ __launch_bounds__(256) void scan3_kernel() {
    const int seg  = blockIdx.x;
    const int base = seg * SCAN_SEG_LEN;
    const int tid  = threadIdx.x;
    __shared__ int sums[256];
    __shared__ int segbase;

    if (tid == 0) {
        int b = seg / SCAN_SEGS;
        int s = 0;
        for (int k = b * SCAN_SEGS; k < seg; k++) s += g_segsum[k];
        segbase = s;
    }

    int vals[SCAN_PER_THR];
    int tb = tid * SCAN_PER_THR;
    int local = 0;
#pragma unroll
    for (int i = 0; i < SCAN_PER_THR; i++) {
        int idx = tb + i;
        vals[i] = (idx < SCAN_SEG_LEN) ? g_counts[base + idx] : 0;
        local += vals[i];
    }
    int v = local;
    int lane = tid & 31, w = tid >> 5;
#pragma unroll
    for (int o = 1; o < 32; o <<= 1) {
        int u = __shfl_up_sync(0xffffffffu, v, o);
        if (lane >= o) v += u;
    }
    __shared__ int wsum[8];
    if (lane == 31) wsum[w] = v;
    __syncthreads();
    if (tid < 8) {
        int u = wsum[tid];
#pragma unroll
        for (int o = 1; o < 8; o <<= 1) {
            int p = __shfl_up_sync(0xffu, u, o);
            if (tid >= o) u += p;
        }
        sums[tid] = u;
    }
    __syncthreads();
    int prefix = v - local + (w > 0 ? sums[w - 1] : 0) + segbase;
#pragma unroll
    for (int i = 0; i < SCAN_PER_THR; i++) {
        int idx = tb + i;
        if (idx < SCAN_SEG_LEN) {
            g_offsets[base + idx] = prefix;
            prefix += vals[i];
        }
    }
}

// ---------------------------------------------------------------------------
// 4) fill CSR buckets: atomically bump g_offsets itself (post-fill it = END).
// ---------------------------------------------------------------------------
__global__ __launch_bounds__(256) void fill_kernel(const int* __restrict__ ei) {
    int b = blockIdx.y;
    int e = blockIdx.x * 256 + threadIdx.x;
    if (e >= E_) return;
    int src = ei[(size_t)b * 2 * E_ + e];
    int trg = ei[(size_t)b * 2 * E_ + E_ + e];
    int pos = atomicAdd(&g_offsets[b * N_ + trg], 1);
    g_sorted_src[(size_t)b * E_ + pos] = src;
}

// ---------------------------------------------------------------------------
// 5) gather-aggregate: one warp per node, all 8 heads, unroll-4.
// ---------------------------------------------------------------------------
__global__ __launch_bounds__(256) void aggregate_kernel(float* __restrict__ out) {
    const int tid  = threadIdx.x;
    const int wid  = tid >> 5;
    const int lane = tid & 31;
    const int n    = blockIdx.x * 8 + wid;
    const int b    = blockIdx.y;

    __shared__ int   s_src[8][32];
    __shared__ float s_w[8][32][8];

    const int deg = g_counts[b * N_ + n];
    const int off = g_offsets[b * N_ + n] - deg;   // offsets = end after fill

    const float4 at0 = *(const float4*)(g_atrg + (size_t)(b * N_ + n) * H_);
    const float4 at1 = *(const float4*)(g_atrg + (size_t)(b * N_ + n) * H_ + 4);

    const int*    srcs = g_sorted_src + (size_t)b * E_ + off;
    const float*  asb  = g_asrc + (size_t)b * N_ * H_;
    const __half* hpb  = g_hp16 + (size_t)b * N_ * 256;

    const int hgrp = lane >> 3;
    const int dofs = 4 * lane;

    float4 acc0 = make_float4(0.f, 0.f, 0.f, 0.f);
    float4 acc1 = make_float4(0.f, 0.f, 0.f, 0.f);
    float  den0 = 0.f, den1 = 0.f;

    for (int c0 = 0; c0 < deg; c0 += 32) {
        const int cnt = min(32, deg - c0);
        if (lane < cnt) {
            int src = __ldg(srcs + c0 + lane);
            s_src[wid][lane] = src;
            const float4 a0 = *(const float4*)(asb + (size_t)src * H_);
            const float4 a1 = *(const float4*)(asb + (size_t)src * H_ + 4);
            s_w[wid][lane][0] = leaky_exp(a0.x + at0.x);
            s_w[wid][lane][2] = leaky_exp(a0.y + at0.y);
            s_w[wid][lane][4] = leaky_exp(a0.z + at0.z);
            s_w[wid][lane][6] = leaky_exp(a0.w + at0.w);
            s_w[wid][lane][1] = leaky_exp(a1.x + at1.x);
            s_w[wid][lane][3] = leaky_exp(a1.y + at1.y);
            s_w[wid][lane][5] = leaky_exp(a1.z + at1.z);
            s_w[wid][lane][7] = leaky_exp(a1.w + at1.w);
        }
        __syncwarp();

        int j = 0;
        for (; j + 4 <= cnt; j += 4) {
            int   sA = s_src[wid][j],     sB = s_src[wid][j + 1];
            int   sC = s_src[wid][j + 2], sD = s_src[wid][j + 3];
            float2 wA = *(const float2*)&s_w[wid][j][2 * hgrp];
            float2 wB = *(const float2*)&s_w[wid][j + 1][2 * hgrp];
            float2 wC = *(const float2*)&s_w[wid][j + 2][2 * hgrp];
            float2 wD = *(const float2*)&s_w[wid][j + 3][2 * hgrp];
            const __half* rA = hpb + (size_t)sA * 256 + dofs;
            const __half* rB = hpb + (size_t)sB * 256 + dofs;
            const __half* rC = hpb + (size_t)sC * 256 + dofs;
            const __half* rD = hpb + (size_t)sD * 256 + dofs;
            uint2 pA0 = __ldg((const uint2*)rA);
            uint2 pA1 = __ldg((const uint2*)(rA + 128));
            uint2 pB0 = __ldg((const uint2*)rB);
            uint2 pB1 = __ldg((const uint2*)(rB + 128));
            uint2 pC0 = __ldg((const uint2*)rC);
            uint2 pC1 = __ldg((const uint2*)(rC + 128));
            uint2 pD0 = __ldg((const uint2*)rD);
            uint2 pD1 = __ldg((const uint2*)(rD + 128));
            den0 += (wA.x + wB.x) + (wC.x + wD.x);
            den1 += (wA.y + wB.y) + (wC.y + wD.y);
            float2 v0, v1, v2, v3;
            v0 = __half22float2(*(__half2*)&pA0.x); v1 = __half22float2(*(__half2*)&pA0.y);
            v2 = __half22float2(*(__half2*)&pA1.x); v3 = __half22float2(*(__half2*)&pA1.y);
            acc0.x = fmaf(wA.x, v0.x, acc0.x); acc0.y = fmaf(wA.x, v0.y, acc0.y);
            acc0.z = fmaf(wA.x, v1.x, acc0.z); acc0.w = fmaf(wA.x, v1.y, acc0.w);
            acc1.x = fmaf(wA.y, v2.x, acc1.x); acc1.y = fmaf(wA.y, v2.y, acc1.y);
            acc1.z = fmaf(wA.y, v3.x, acc1.z); acc1.w = fmaf(wA.y, v3.y, acc1.w);
            v0 = __half22float2(*(__half2*)&pB0.x); v1 = __half22float2(*(__half2*)&pB0.y);
            v2 = __half22float2(*(__half2*)&pB1.x); v3 = __half22float2(*(__half2*)&pB1.y);
            acc0.x = fmaf(wB.x, v0.x, acc0.x); acc0.y = fmaf(wB.x, v0.y, acc0.y);
            acc0.z = fmaf(wB.x, v1.x, acc0.z); acc0.w = fmaf(wB.x, v1.y, acc0.w);
            acc1.x = fmaf(wB.y, v2.x, acc1.x); acc1.y = fmaf(wB.y, v2.y, acc1.y);
            acc1.z = fmaf(wB.y, v3.x, acc1.z); acc1.w = fmaf(wB.y, v3.y, acc1.w);
            v0 = __half22float2(*(__half2*)&pC0.x); v1 = __half22float2(*(__half2*)&pC0.y);
            v2 = __half22float2(*(__half2*)&pC1.x); v3 = __half22float2(*(__half2*)&pC1.y);
            acc0.x = fmaf(wC.x, v0.x, acc0.x); acc0.y = fmaf(wC.x, v0.y, acc0.y);
            acc0.z = fmaf(wC.x, v1.x, acc0.z); acc0.w = fmaf(wC.x, v1.y, acc0.w);
            acc1.x = fmaf(wC.y, v2.x, acc1.x); acc1.y = fmaf(wC.y, v2.y, acc1.y);
            acc1.z = fmaf(wC.y, v3.x, acc1.z); acc1.w = fmaf(wC.y, v3.y, acc1.w);
            v0 = __half22float2(*(__half2*)&pD0.x); v1 = __half22float2(*(__half2*)&pD0.y);
            v2 = __half22float2(*(__half2*)&pD1.x); v3 = __half22float2(*(__half2*)&pD1.y);
            acc0.x = fmaf(wD.x, v0.x, acc0.x); acc0.y = fmaf(wD.x, v0.y, acc0.y);
            acc0.z = fmaf(wD.x, v1.x, acc0.z); acc0.w = fmaf(wD.x, v1.y, acc0.w);
            acc1.x = fmaf(wD.y, v2.x, acc1.x); acc1.y = fmaf(wD.y, v2.y, acc1.y);
            acc1.z = fmaf(wD.y, v3.x, acc1.z); acc1.w = fmaf(wD.y, v3.y, acc1.w);
        }
        for (; j < cnt; j++) {
            const int s = s_src[wid][j];
            const float2 w = *(const float2*)&s_w[wid][j][2 * hgrp];
            const __half* rr = hpb + (size_t)s * 256 + dofs;
            uint2 p0 = __ldg((const uint2*)rr);
            uint2 p1 = __ldg((const uint2*)(rr + 128));
            den0 += w.x; den1 += w.y;
            float2 a0 = __half22float2(*(__half2*)&p0.x);
            float2 a1 = __half22float2(*(__half2*)&p0.y);
            float2 a2 = __half22float2(*(__half2*)&p1.x);
            float2 a3 = __half22float2(*(__half2*)&p1.y);
            acc0.x = fmaf(w.x, a0.x, acc0.x); acc0.y = fmaf(w.x, a0.y, acc0.y);
            acc0.z = fmaf(w.x, a1.x, acc0.z); acc0.w = fmaf(w.x, a1.y, acc0.w);
            acc1.x = fmaf(w.y, a2.x, acc1.x); acc1.y = fmaf(w.y, a2.y, acc1.y);
            acc1.z = fmaf(w.y, a3.x, acc1.z); acc1.w = fmaf(w.y, a3.y, acc1.w);
        }
        __syncwarp();
    }

    const float i0 = 1.f / (den0 + 1e-16f);
    const float i1 = 1.f / (den1 + 1e-16f);
    const int d0 = 4 * (lane & 7);
    float4* o0 = (float4*)(out + (((size_t)b * H_ + hgrp) * N_ + n) * D_ + d0);
    float4* o1 = (float4*)(out + (((size_t)b * H_ + hgrp + 4) * N_ + n) * D_ + d0);
    *o0 = make_float4(acc0.x * i0, acc0.y * i0, acc0.z * i0, acc0.w * i0);
    *o1 = make_float4(acc1.x * i1, acc1.y * i1, acc1.z * i1, acc1.w * i1);
}

// ---------------------------------------------------------------------------
// kernel_launch — simple 2-stream fork (proven best schedule).
// ---------------------------------------------------------------------------
extern "C" void kernel_launch(void* const* d_in, const int* in_sizes, int n_in,
                              void* d_out, int out_size) {
    const float* h        = (const float*)d_in[0];
    const int*   ei       = (const int*)d_in[1];
    const float* W        = (const float*)d_in[2];
    const float* attn_src = (const float*)d_in[3];
    const float* attn_trg = (const float*)d_in[4];
    float*       out      = (float*)d_out;

    static cudaStream_t s_side = nullptr;
    static cudaEvent_t  ev_fork = nullptr, ev_join = nullptr;
    if (s_side == nullptr) {
        cudaStreamCreateWithFlags(&s_side, cudaStreamNonBlocking);
        cudaEventCreateWithFlags(&ev_fork, cudaEventDisableTiming);
        cudaEventCreateWithFlags(&ev_join, cudaEventDisableTiming);
    }

    // fork
    cudaEventRecord(ev_fork, 0);
    cudaStreamWaitEvent(s_side, ev_fork, 0);

    // side stream: edge prep
    dim3 egrid((E_ + 255) / 256, B_);
    init_kernel<<<(M_ + 255) / 256, 256, 0, s_side>>>();
    hist_kernel<<<egrid, 256, 0, s_side>>>(ei);
    scan1_kernel<<<B_ * SCAN_SEGS, 256, 0, s_side>>>();
    scan3_kernel<<<B_ * SCAN_SEGS, 256, 0, s_side>>>();
    fill_kernel<<<egrid, 256, 0, s_side>>>(ei);
    cudaEventRecord(ev_join, s_side);

    // main stream: GEMM (+ fused projections)
    dim3 ggrid(M_ / 128, 256 / 128);
    gemm_fp16_kernel<<<ggrid, 256>>>(h, W, attn_src, attn_trg);

    // join, then aggregate
    cudaStreamWaitEvent(0, ev_join, 0);
    dim3 agrid(N_ / 8, B_);
    aggregate_kernel<<<agrid, 256>>>(out);
}